// round 1
// baseline (speedup 1.0000x reference)
#include <cuda_runtime.h>
#include <math.h>

// Problem constants
#define BATCH 8
#define CIN   96
#define COUT  192
#define NTOK  3136            // 56*56
#define NPOS  (BATCH * NTOK)  // 25088 positions for BN stats

// ---------------- scratch (static device globals; no allocs allowed) -------
__device__ float d_xj[BATCH * CIN * NTOK];     // relu(x - att), channel-major
__device__ float d_y[BATCH * COUT * NTOK];     // pre-BN conv output
__device__ float d_stats[2 * COUT];            // [0:192) sum, [192:384) sumsq

// ============================ attention kernel =============================
// Flash-attention style: per CTA one 64-row block of one batch.
// Q,K,V are all the token matrix x[b] viewed as [N, C] (transpose of storage).
#define BM 64
#define BN 64
#define QPAD 100               // row stride for Qs/Ks (floats), mult of 4
#define ATT_THREADS 256
#define NTILES (NTOK / BN)     // 49

__global__ __launch_bounds__(ATT_THREADS, 2)
void attn_kernel(const float* __restrict__ x, float* __restrict__ xj)
{
    const int b   = blockIdx.y;
    const int n0  = blockIdx.x * BM;
    const int tid = threadIdx.x;
    const int tx  = tid & 15;
    const int ty  = tid >> 4;

    extern __shared__ float sm[];
    float* Qs    = sm;                       // BM * QPAD
    float* Ks    = Qs + BM * QPAD;           // BN * QPAD
    float* Ps    = Ks + BN * QPAD;           // BM * BN
    float* m_sm  = Ps + BM * BN;             // BM
    float* l_sm  = m_sm + BM;                // BM
    float* al_sm = l_sm + BM;                // BM

    const float* xb = x + (size_t)b * CIN * NTOK;

    // load Q block [64 rows x 96 ch]  (Qs[r][c] = x[b][c][n0+r])
    for (int idx = tid; idx < CIN * BM; idx += ATT_THREADS) {
        int c = idx >> 6, r = idx & 63;
        Qs[r * QPAD + c] = xb[c * NTOK + n0 + r];
    }
    if (tid < BM) { m_sm[tid] = -3.0e38f; l_sm[tid] = 0.0f; }

    float o[4][6];
    #pragma unroll
    for (int ii = 0; ii < 4; ++ii)
        #pragma unroll
        for (int cc = 0; cc < 6; ++cc) o[ii][cc] = 0.0f;

    for (int t = 0; t < NTILES; ++t) {
        const int n1 = t * BN;
        __syncthreads();   // Ks (V) reads from previous iteration done
        for (int idx = tid; idx < CIN * BN; idx += ATT_THREADS) {
            int c = idx >> 6, r = idx & 63;
            Ks[r * QPAD + c] = xb[c * NTOK + n1 + r];
        }
        __syncthreads();

        // ---- GEMM1: S = Q_blk * K_tile^T  (4x4 per thread) ----
        float s[4][4];
        #pragma unroll
        for (int ii = 0; ii < 4; ++ii)
            #pragma unroll
            for (int jj = 0; jj < 4; ++jj) s[ii][jj] = 0.0f;

        #pragma unroll 2
        for (int k = 0; k < CIN; k += 4) {
            float4 qa[4], kb[4];
            #pragma unroll
            for (int ii = 0; ii < 4; ++ii)
                qa[ii] = *(const float4*)&Qs[(ty + 16 * ii) * QPAD + k];
            #pragma unroll
            for (int jj = 0; jj < 4; ++jj)
                kb[jj] = *(const float4*)&Ks[(tx + 16 * jj) * QPAD + k];
            #pragma unroll
            for (int ii = 0; ii < 4; ++ii)
                #pragma unroll
                for (int jj = 0; jj < 4; ++jj) {
                    s[ii][jj] = fmaf(qa[ii].x, kb[jj].x, s[ii][jj]);
                    s[ii][jj] = fmaf(qa[ii].y, kb[jj].y, s[ii][jj]);
                    s[ii][jj] = fmaf(qa[ii].z, kb[jj].z, s[ii][jj]);
                    s[ii][jj] = fmaf(qa[ii].w, kb[jj].w, s[ii][jj]);
                }
        }

        // ---- online softmax in register layout (row i spread over 16 lanes) ----
        #pragma unroll
        for (int ii = 0; ii < 4; ++ii) {
            const int i = ty + 16 * ii;
            float mx = fmaxf(fmaxf(s[ii][0], s[ii][1]), fmaxf(s[ii][2], s[ii][3]));
            #pragma unroll
            for (int off = 8; off > 0; off >>= 1)
                mx = fmaxf(mx, __shfl_xor_sync(0xffffffffu, mx, off, 16));
            const float mo = m_sm[i];
            const float mn = fmaxf(mo, mx);
            float rs = 0.0f;
            #pragma unroll
            for (int jj = 0; jj < 4; ++jj) {
                float p = __expf(s[ii][jj] - mn);
                s[ii][jj] = p;
                rs += p;
            }
            #pragma unroll
            for (int off = 8; off > 0; off >>= 1)
                rs += __shfl_xor_sync(0xffffffffu, rs, off, 16);
            if (tx == 0) {
                float al = __expf(mo - mn);
                al_sm[i] = al;
                l_sm[i]  = l_sm[i] * al + rs;
                m_sm[i]  = mn;
            }
            #pragma unroll
            for (int jj = 0; jj < 4; ++jj)
                Ps[i * BN + tx + 16 * jj] = s[ii][jj];
        }
        __syncthreads();

        // ---- rescale O, then GEMM2: O += P * V  (V = Ks) (4x6 per thread) ----
        #pragma unroll
        for (int ii = 0; ii < 4; ++ii) {
            const float al = al_sm[ty + 16 * ii];
            #pragma unroll
            for (int cc = 0; cc < 6; ++cc) o[ii][cc] *= al;
        }
        #pragma unroll 2
        for (int k = 0; k < BN; k += 4) {
            float4 p4[4];
            #pragma unroll
            for (int ii = 0; ii < 4; ++ii)
                p4[ii] = *(const float4*)&Ps[(ty + 16 * ii) * BN + k];
            #pragma unroll
            for (int kk = 0; kk < 4; ++kk) {
                float vb[6];
                #pragma unroll
                for (int cc = 0; cc < 6; ++cc)
                    vb[cc] = Ks[(k + kk) * QPAD + tx + 16 * cc];
                #pragma unroll
                for (int ii = 0; ii < 4; ++ii) {
                    const float pv = ((const float*)&p4[ii])[kk];
                    #pragma unroll
                    for (int cc = 0; cc < 6; ++cc)
                        o[ii][cc] = fmaf(pv, vb[cc], o[ii][cc]);
                }
            }
        }
    }
    __syncthreads();

    // finalize O = acc / l, stage in Ks, then write xj = relu(x - O)
    #pragma unroll
    for (int ii = 0; ii < 4; ++ii) {
        const int i = ty + 16 * ii;
        const float inv = 1.0f / l_sm[i];
        #pragma unroll
        for (int cc = 0; cc < 6; ++cc)
            Ks[i * QPAD + tx + 16 * cc] = o[ii][cc] * inv;
    }
    __syncthreads();

    float* xjb = xj + (size_t)b * CIN * NTOK;
    for (int idx = tid; idx < CIN * BM; idx += ATT_THREADS) {
        int c = idx >> 6, r = idx & 63;
        float v = Qs[r * QPAD + c] - Ks[r * QPAD + c];
        xjb[c * NTOK + n0 + r] = fmaxf(v, 0.0f);
    }
}

// ============================ conv (1x1) kernel ============================
// y[b][o][n] = bias[o] + sum_c W[o][c] * cat[b][c][n]; cat = [x ; xj]
// also accumulates per-channel sum / sumsq for BN.
#define OT 64
#define NT 224
#define KC 32
#define CONV_THREADS 256

__global__ __launch_bounds__(CONV_THREADS, 2)
void conv_kernel(const float* __restrict__ x, const float* __restrict__ xj,
                 const float* __restrict__ w, const float* __restrict__ bias,
                 float* __restrict__ y, float* __restrict__ stats)
{
    const int b  = blockIdx.z;
    const int o0 = blockIdx.y * OT;
    const int nb = blockIdx.x * NT;
    const int tid = threadIdx.x;
    const int tx  = tid & 15;
    const int ty  = tid >> 4;

    extern __shared__ float sm[];
    float* Wsm = sm;             // OT * COUT floats (64*192)
    float* Xsm = Wsm + OT * COUT;// KC * NT floats (32*224)

    // load this CTA's 64 filter rows (full K=192)
    for (int idx = tid; idx < OT * COUT; idx += CONV_THREADS)
        Wsm[idx] = w[(size_t)(o0 + idx / COUT) * COUT + (idx % COUT)];

    float acc[4][14];
    #pragma unroll
    for (int oo = 0; oo < 4; ++oo) {
        const float bv = bias[o0 + ty + 16 * oo];
        #pragma unroll
        for (int nn = 0; nn < 14; ++nn) acc[oo][nn] = bv;
    }

    for (int kc = 0; kc < COUT; kc += KC) {
        __syncthreads();
        for (int idx = tid; idx < KC * NT; idx += CONV_THREADS) {
            const int k = idx / NT, n = idx % NT;
            const int c = kc + k;
            const float* src = (c < CIN)
                ? (x  + ((size_t)b * CIN + c) * NTOK)
                : (xj + ((size_t)b * CIN + (c - CIN)) * NTOK);
            Xsm[k * NT + n] = src[nb + n];
        }
        __syncthreads();
        #pragma unroll 4
        for (int k = 0; k < KC; ++k) {
            float a[4];
            #pragma unroll
            for (int oo = 0; oo < 4; ++oo)
                a[oo] = Wsm[(ty + 16 * oo) * COUT + kc + k];
            float bx[14];
            #pragma unroll
            for (int nn = 0; nn < 14; ++nn)
                bx[nn] = Xsm[k * NT + tx + 16 * nn];
            #pragma unroll
            for (int oo = 0; oo < 4; ++oo)
                #pragma unroll
                for (int nn = 0; nn < 14; ++nn)
                    acc[oo][nn] = fmaf(a[oo], bx[nn], acc[oo][nn]);
        }
    }

    // store + per-channel partial stats
    float* yb = y + ((size_t)b * COUT + o0) * NTOK + nb;
    #pragma unroll
    for (int oo = 0; oo < 4; ++oo) {
        const int o = ty + 16 * oo;
        float s1 = 0.0f, s2 = 0.0f;
        #pragma unroll
        for (int nn = 0; nn < 14; ++nn) {
            const float v = acc[oo][nn];
            yb[(size_t)o * NTOK + tx + 16 * nn] = v;
            s1 += v;
            s2 += v * v;
        }
        #pragma unroll
        for (int off = 8; off > 0; off >>= 1) {
            s1 += __shfl_xor_sync(0xffffffffu, s1, off, 16);
            s2 += __shfl_xor_sync(0xffffffffu, s2, off, 16);
        }
        if (tx == 0) {
            atomicAdd(&stats[o0 + o], s1);
            atomicAdd(&stats[COUT + o0 + o], s2);
        }
    }
}

// ============================ BN + GELU kernel =============================
__global__ void bn_gelu_kernel(const float* __restrict__ y,
                               const float* __restrict__ stats,
                               const float* __restrict__ gamma,
                               const float* __restrict__ beta,
                               float* __restrict__ out)
{
    const size_t idx = (size_t)blockIdx.x * blockDim.x + threadIdx.x;
    const int o = (int)((idx / NTOK) % COUT);
    const float invN = 1.0f / (float)NPOS;
    const float mean = stats[o] * invN;
    const float var  = stats[COUT + o] * invN - mean * mean;
    const float sc   = rsqrtf(var + 1e-5f);
    float v = (y[idx] - mean) * sc * gamma[o] + beta[o];
    out[idx] = 0.5f * v * (1.0f + erff(v * 0.70710678118654752f));
}

__global__ void zero_stats_kernel(float* stats)
{
    stats[threadIdx.x] = 0.0f;
}

// ================================ launch ===================================
extern "C" void kernel_launch(void* const* d_in, const int* in_sizes, int n_in,
                              void* d_out, int out_size)
{
    const float* x      = (const float*)d_in[0];
    const float* conv_w = (const float*)d_in[1];
    const float* conv_b = (const float*)d_in[2];
    const float* gamma  = (const float*)d_in[3];
    const float* beta   = (const float*)d_in[4];
    float* out = (float*)d_out;

    float *xj, *y, *stats;
    cudaGetSymbolAddress((void**)&xj, d_xj);
    cudaGetSymbolAddress((void**)&y, d_y);
    cudaGetSymbolAddress((void**)&stats, d_stats);

    const int attn_smem = (BM * QPAD + BN * QPAD + BM * BN + 3 * BM) * (int)sizeof(float);
    const int conv_smem = (OT * COUT + KC * NT) * (int)sizeof(float);
    cudaFuncSetAttribute(attn_kernel, cudaFuncAttributeMaxDynamicSharedMemorySize, attn_smem);
    cudaFuncSetAttribute(conv_kernel, cudaFuncAttributeMaxDynamicSharedMemorySize, conv_smem);

    zero_stats_kernel<<<1, 2 * COUT>>>(stats);

    dim3 agrid(NTOK / BM, BATCH);
    attn_kernel<<<agrid, ATT_THREADS, attn_smem>>>(x, xj);

    dim3 cgrid(NTOK / NT, COUT / OT, BATCH);
    conv_kernel<<<cgrid, CONV_THREADS, conv_smem>>>(x, xj, conv_w, conv_b, y, stats);

    const size_t total = (size_t)BATCH * COUT * NTOK;
    bn_gelu_kernel<<<(unsigned)(total / 256), 256>>>(y, stats, gamma, beta, out);
}